// round 6
// baseline (speedup 1.0000x reference)
#include <cuda_runtime.h>
#include <cuda_bf16.h>

// Problem constants
constexpr int B = 4, C = 32, H = 720, W = 720;
constexpr int HW = H * W;              // 518400
constexpr int BHW = B * HW;            // 2073600

// Tiling for fused diag+conv kernel
constexpr int TH  = 8;     // output rows per block
constexpr int TWF = 360;   // output cols per block (W/2)
constexpr int SROWS = TH + 10;   // 18 s rows
constexpr int DROWS = TH + 2;    // 10 d rows
constexpr int SW  = 368;   // smem row width (360 + 8 halo cols)

// Scratch (no cudaMalloc allowed)
__device__ float g_s[BHW];       // channel sum

// K1: s[b,h,w] = sum_c x[b,c,h,w] for ONE batch b (float4 over w, streaming loads)
__global__ __launch_bounds__(256) void k_csum(const float* __restrict__ x, int b) {
    int idx = blockIdx.x * blockDim.x + threadIdx.x;   // over HW/4
    if (idx >= HW / 4) return;
    const float4* xp = reinterpret_cast<const float4*>(x + (size_t)b * C * HW) + idx;
    float4 acc = make_float4(0.f, 0.f, 0.f, 0.f);
    #pragma unroll
    for (int c = 0; c < C; c++) {
        float4 v = __ldcs(&xp[(size_t)c * (HW / 4)]);   // evict-first: x has no reuse
        acc.x += v.x; acc.y += v.y; acc.z += v.z; acc.w += v.w;
    }
    reinterpret_cast<float4*>(g_s + (size_t)b * HW)[idx] = acc;  // s stays L2-resident
}

// K2 (fused, per batch): w2 reduction + 9-tap diagonal average + 3-tap broadcast conv
__global__ __launch_bounds__(256) void k_fused(const float* __restrict__ cw,
                                               float* __restrict__ out, int b) {
    __shared__ __align__(16) float s_sm[SROWS][SW];
    __shared__ __align__(16) float d_sm[DROWS][SW];
    __shared__ float sw[C * 3];

    int tid = threadIdx.x;
    // Per-block w2 reduction: w2[o,kh] = sum_i conv_w[o,i,kh,0]  (L2-hit reads)
    if (tid < C * 3) {
        int o = tid / 3, kh = tid % 3;
        float acc = 0.f;
        #pragma unroll
        for (int i = 0; i < C; i++) acc += __ldg(&cw[o * (C * 3) + i * 3 + kh]);
        sw[tid] = acc;
    }

    int h0 = blockIdx.y * TH;
    int w0 = blockIdx.x * TWF;
    const float* sb = g_s + (size_t)b * HW;

    // Stage 1: load s tile [h0-5 .. h0+TH+4] x [w0-4 .. w0+TWF+3] (zero pad OOB)
    for (int t = tid; t < SROWS * (SW / 4); t += 256) {
        int i = t / (SW / 4);
        int v = t % (SW / 4);
        int gr = h0 - 5 + i;
        int gc = w0 - 4 + 4 * v;
        float4 val = make_float4(0.f, 0.f, 0.f, 0.f);
        if (gr >= 0 && gr < H && gc >= 0 && gc + 3 < W)
            val = *reinterpret_cast<const float4*>(sb + gr * W + gc);
        *reinterpret_cast<float4*>(&s_sm[i][4 * v]) = val;
    }
    __syncthreads();

    // Stage 2: d tile rows r = h0-1 .. h0+TH (zero if r outside image)
    for (int t = tid; t < DROWS * TWF; t += 256) {
        int k  = t / TWF;
        int cc = t % TWF;
        int r = h0 - 1 + k;
        float acc = 0.f;
        if (r >= 0 && r < H) {
            #pragma unroll
            for (int j = 0; j < 9; j++) acc += s_sm[k + j][cc + j];
            acc *= (1.0f / 9.0f);
        }
        d_sm[k][cc] = acc;
    }
    __syncthreads();

    // Stage 3: out[b,o,h,w] = sum_kh w2[o,kh] * d[h-1+kh, w], streaming stores
    for (int t = tid; t < TH * (TWF / 4); t += 256) {
        int k2 = t / (TWF / 4);
        int cf = t % (TWF / 4);
        int h  = h0 + k2;
        int wc = w0 + 4 * cf;

        float4 d0 = *reinterpret_cast<const float4*>(&d_sm[k2    ][4 * cf]);
        float4 d1 = *reinterpret_cast<const float4*>(&d_sm[k2 + 1][4 * cf]);
        float4 d2 = *reinterpret_cast<const float4*>(&d_sm[k2 + 2][4 * cf]);

        float* op = out + (size_t)b * C * HW + h * W + wc;
        #pragma unroll
        for (int o = 0; o < C; o++) {
            float a0 = sw[3 * o], a1 = sw[3 * o + 1], a2 = sw[3 * o + 2];
            float4 rv;
            rv.x = a0 * d0.x + a1 * d1.x + a2 * d2.x;
            rv.y = a0 * d0.y + a1 * d1.y + a2 * d2.y;
            rv.z = a0 * d0.z + a1 * d1.z + a2 * d2.z;
            rv.w = a0 * d0.w + a1 * d1.w + a2 * d2.w;
            __stcs(reinterpret_cast<float4*>(op + (size_t)o * HW), rv);
        }
    }
}

// Persistent capture-safe resources (created once on first call; the captured
// work sequence is identical on every call).
static cudaStream_t g_s2 = nullptr;
static cudaEvent_t  g_evc[B];
static cudaEvent_t  g_evj = nullptr;

static void ensure_resources() {
    if (g_s2 == nullptr) {
        cudaStreamCreateWithFlags(&g_s2, cudaStreamNonBlocking);
        for (int i = 0; i < B; i++)
            cudaEventCreateWithFlags(&g_evc[i], cudaEventDisableTiming);
        cudaEventCreateWithFlags(&g_evj, cudaEventDisableTiming);
    }
}

extern "C" void kernel_launch(void* const* d_in, const int* in_sizes, int n_in,
                              void* d_out, int out_size) {
    const float* x  = (const float*)d_in[0];   // (4,32,720,720)
    const float* cw = (const float*)d_in[1];   // (32,32,3,1)
    float* out = (float*)d_out;                // (4,32,720,720)

    ensure_resources();

    const int csum_blocks = (HW / 4 + 255) / 256;   // 507
    dim3 fgrid(W / TWF, H / TH, 1);                 // (2, 90)

    // Pipeline by batch: csum(b) on default stream, fused(b) on g_s2 (overlap
    // read-heavy csum(b+1..) with write-heavy fused(b)).
    for (int b = 0; b < B; b++) {
        k_csum<<<csum_blocks, 256, 0, 0>>>(x, b);
        cudaEventRecord(g_evc[b], 0);
    }
    for (int b = 0; b < B; b++) {
        cudaStreamWaitEvent(g_s2, g_evc[b], 0);
        k_fused<<<fgrid, 256, 0, g_s2>>>(cw, out, b);
    }
    // Join back to the default (capture) stream.
    cudaEventRecord(g_evj, g_s2);
    cudaStreamWaitEvent(0, g_evj, 0);
}

// round 8
// speedup vs baseline: 1.2649x; 1.2649x over previous
#include <cuda_runtime.h>
#include <cuda_bf16.h>

// Problem constants
constexpr int B = 4, C = 32, H = 720, W = 720;
constexpr int HW = H * W;              // 518400
constexpr int BHW = B * HW;            // 2073600

// Tiling for fused diag+conv kernel (sized for 8 blocks/SM: ~28KB smem)
constexpr int TH  = 8;     // output rows per block
constexpr int TWF = 240;   // output cols per block (W/3)
constexpr int SROWS = TH + 10;   // 18 s rows (halo: d needs ±1 rows, each d row ±4 diag)
constexpr int DROWS = TH + 2;    // 10 d rows
constexpr int SW  = 248;   // smem row width (240 + 8 halo cols)

// Scratch (no cudaMalloc allowed)
__device__ float g_s[BHW];       // channel sum

// K1: s[b,h,w] = sum_c x[b,c,h,w]  (float4 over w, streaming loads, full grid)
__global__ __launch_bounds__(256) void k_csum(const float* __restrict__ x) {
    int idx = blockIdx.x * blockDim.x + threadIdx.x;   // over BHW/4
    if (idx >= BHW / 4) return;
    int base = idx * 4;
    int b = base / HW;
    int hw = base % HW;
    const float4* xp = reinterpret_cast<const float4*>(x + (size_t)b * C * HW + hw);
    float4 acc = make_float4(0.f, 0.f, 0.f, 0.f);
    #pragma unroll
    for (int c = 0; c < C; c++) {
        float4 v = __ldcs(&xp[(size_t)c * (HW / 4)]);   // evict-first: x has no reuse
        acc.x += v.x; acc.y += v.y; acc.z += v.z; acc.w += v.w;
    }
    reinterpret_cast<float4*>(g_s)[idx] = acc;          // s stays L2-resident
}

// K2 (fused): w2 reduction + 9-tap diagonal average of s + 3-tap broadcast conv
__global__ __launch_bounds__(256) void k_fused(const float* __restrict__ cw,
                                               float* __restrict__ out) {
    __shared__ __align__(16) float s_sm[SROWS][SW];
    __shared__ __align__(16) float d_sm[DROWS][SW];
    __shared__ float sw[C * 3];

    int tid = threadIdx.x;
    // Per-block w2 reduction: w2[o,kh] = sum_i conv_w[o,i,kh,0]  (L2-hit reads)
    if (tid < C * 3) {
        int o = tid / 3, kh = tid % 3;
        float acc = 0.f;
        #pragma unroll
        for (int i = 0; i < C; i++) acc += __ldg(&cw[o * (C * 3) + i * 3 + kh]);
        sw[tid] = acc;
    }

    int b  = blockIdx.z;
    int h0 = blockIdx.y * TH;
    int w0 = blockIdx.x * TWF;
    const float* sb = g_s + (size_t)b * HW;

    // Stage 1: load s tile [h0-5 .. h0+TH+4] x [w0-4 .. w0+TWF+3] (zero pad OOB)
    for (int t = tid; t < SROWS * (SW / 4); t += 256) {
        int i = t / (SW / 4);
        int v = t % (SW / 4);
        int gr = h0 - 5 + i;
        int gc = w0 - 4 + 4 * v;       // 16B aligned (w0 % 4 == 0)
        float4 val = make_float4(0.f, 0.f, 0.f, 0.f);
        if (gr >= 0 && gr < H && gc >= 0 && gc + 3 < W)
            val = *reinterpret_cast<const float4*>(sb + gr * W + gc);
        *reinterpret_cast<float4*>(&s_sm[i][4 * v]) = val;
    }
    __syncthreads();

    // Stage 2: d tile rows r = h0-1 .. h0+TH (zero if r outside image)
    for (int t = tid; t < DROWS * TWF; t += 256) {
        int k  = t / TWF;
        int cc = t % TWF;
        int r = h0 - 1 + k;
        float acc = 0.f;
        if (r >= 0 && r < H) {
            #pragma unroll
            for (int j = 0; j < 9; j++) acc += s_sm[k + j][cc + j];
            acc *= (1.0f / 9.0f);
        }
        d_sm[k][cc] = acc;
    }
    __syncthreads();

    // Stage 3: out[b,o,h,w] = sum_kh w2[o,kh] * d[h-1+kh, w], streaming stores
    for (int t = tid; t < TH * (TWF / 4); t += 256) {
        int k2 = t / (TWF / 4);
        int cf = t % (TWF / 4);
        int h  = h0 + k2;
        int wc = w0 + 4 * cf;

        float4 d0 = *reinterpret_cast<const float4*>(&d_sm[k2    ][4 * cf]);
        float4 d1 = *reinterpret_cast<const float4*>(&d_sm[k2 + 1][4 * cf]);
        float4 d2 = *reinterpret_cast<const float4*>(&d_sm[k2 + 2][4 * cf]);

        float* op = out + (size_t)b * C * HW + h * W + wc;
        #pragma unroll
        for (int o = 0; o < C; o++) {
            float a0 = sw[3 * o], a1 = sw[3 * o + 1], a2 = sw[3 * o + 2];
            float4 rv;
            rv.x = a0 * d0.x + a1 * d1.x + a2 * d2.x;
            rv.y = a0 * d0.y + a1 * d1.y + a2 * d2.y;
            rv.z = a0 * d0.z + a1 * d1.z + a2 * d2.z;
            rv.w = a0 * d0.w + a1 * d1.w + a2 * d2.w;
            __stcs(reinterpret_cast<float4*>(op + (size_t)o * HW), rv);
        }
    }
}

extern "C" void kernel_launch(void* const* d_in, const int* in_sizes, int n_in,
                              void* d_out, int out_size) {
    const float* x  = (const float*)d_in[0];   // (4,32,720,720)
    const float* cw = (const float*)d_in[1];   // (32,32,3,1)
    float* out = (float*)d_out;                // (4,32,720,720)

    {
        int n = BHW / 4;
        k_csum<<<(n + 255) / 256, 256>>>(x);
    }

    dim3 grid(W / TWF, H / TH, B);             // (3, 90, 4) = 1080 blocks
    k_fused<<<grid, 256>>>(cw, out);
}